// round 4
// baseline (speedup 1.0000x reference)
#include <cuda_runtime.h>
#include <cuda_bf16.h>

#define NMAX 100000
#define EMAX 1600000

// ---- device scratch (no allocations allowed) ----
static __device__ float g_xh[NMAX * 128];      // projected features [N,128]
static __device__ float g_asrc[NMAX * 8];      // per-node src logits [N,H]
static __device__ float g_adst[NMAX * 8];      // per-node dst logits [N,H]
static __device__ int   g_cnt[NMAX];           // in-degree histogram
static __device__ int   g_off[NMAX + 1];       // CSR offsets
static __device__ int   g_cur[NMAX];           // scatter cursors
static __device__ int   g_blk[128];            // scan partials
static __device__ int   g_blkscan[128];        // scanned partials
static __device__ int   g_sorted[EMAX];        // src ids grouped by dst

// ---------------------------------------------------------------------------
__global__ void zero_kernel(int n) {
    int i = blockIdx.x * blockDim.x + threadIdx.x;
    if (i < n) g_cnt[i] = 0;
}

// ---------------------------------------------------------------------------
// xh = x @ W^T + b     (out[n,j] = sum_k x[n,k] * W[j,k] + b[j])
// 64-row x 128-col tile per block, 256 threads, 8x4 micro-tile per thread.
__global__ __launch_bounds__(256) void gemm_kernel(
    const float* __restrict__ x, const float* __restrict__ W,
    const float* __restrict__ b, int n)
{
    __shared__ float ws[32 * 129];   // ws[k'][j] = W[j][kk+k'], padded rows
    __shared__ float xs[64 * 32];    // xs[r][k']
    const int tid = threadIdx.x;
    const int tx = tid & 31, ty = tid >> 5;
    const int row0 = blockIdx.x * 64;

    float acc[8][4];
#pragma unroll
    for (int r = 0; r < 8; r++)
#pragma unroll
        for (int c = 0; c < 4; c++) acc[r][c] = 0.f;

    for (int kk = 0; kk < 128; kk += 32) {
#pragma unroll
        for (int i = 0; i < 16; i++) {              // 4096 W elems
            int idx = tid + i * 256;
            int j = idx >> 5, kq = idx & 31;
            ws[kq * 129 + j] = W[j * 128 + kk + kq];
        }
#pragma unroll
        for (int i = 0; i < 8; i++) {               // 2048 x elems
            int idx = tid + i * 256;
            int r = idx >> 5, kq = idx & 31;
            int row = row0 + r;
            xs[r * 32 + kq] = (row < n) ? x[row * 128 + kk + kq] : 0.f;
        }
        __syncthreads();
#pragma unroll
        for (int kq = 0; kq < 32; kq++) {
            float bv[4];
#pragma unroll
            for (int c = 0; c < 4; c++) bv[c] = ws[kq * 129 + c * 32 + tx];
#pragma unroll
            for (int r = 0; r < 8; r++) {
                float a = xs[(ty * 8 + r) * 32 + kq];
#pragma unroll
                for (int c = 0; c < 4; c++) acc[r][c] += a * bv[c];
            }
        }
        __syncthreads();
    }
#pragma unroll
    for (int r = 0; r < 8; r++) {
        int row = row0 + ty * 8 + r;
        if (row < n) {
#pragma unroll
            for (int c = 0; c < 4; c++) {
                int col = c * 32 + tx;
                g_xh[row * 128 + col] = acc[r][c] + b[col];
            }
        }
    }
}

// ---------------------------------------------------------------------------
// a_src[n,h] = sum_d xh[n,h,d]*att_src[h,d];  same for a_dst.  Warp per node.
__global__ void att_kernel(const float* __restrict__ att_s,
                           const float* __restrict__ att_d, int n)
{
    int warp = (blockIdx.x * blockDim.x + threadIdx.x) >> 5;
    int lane = threadIdx.x & 31;
    if (warp >= n) return;
    float4 xv = *(const float4*)&g_xh[warp * 128 + lane * 4];
    float4 sa = *(const float4*)&att_s[lane * 4];
    float4 da = *(const float4*)&att_d[lane * 4];
    float s = xv.x * sa.x + xv.y * sa.y + xv.z * sa.z + xv.w * sa.w;
    float d = xv.x * da.x + xv.y * da.y + xv.z * da.z + xv.w * da.w;
    s += __shfl_xor_sync(0xffffffffu, s, 1);
    s += __shfl_xor_sync(0xffffffffu, s, 2);
    d += __shfl_xor_sync(0xffffffffu, d, 1);
    d += __shfl_xor_sync(0xffffffffu, d, 2);
    if ((lane & 3) == 0) {
        g_asrc[warp * 8 + (lane >> 2)] = s;
        g_adst[warp * 8 + (lane >> 2)] = d;
    }
}

// ---------------------------------------------------------------------------
__global__ void hist_kernel(const int* __restrict__ ei, int ne) {
    int i = blockIdx.x * blockDim.x + threadIdx.x;
    if (i < ne) atomicAdd(&g_cnt[ei[ne + i]], 1);   // dst = edge_index[1]
}

// ---- 3-step exclusive scan over g_cnt (chunks of 1024) --------------------
__global__ void scan_a(int n) {
    __shared__ int sd[32];
    int t = threadIdx.x;
    int idx = blockIdx.x * 1024 + t;
    int v = (idx < n) ? g_cnt[idx] : 0;
#pragma unroll
    for (int d = 16; d; d >>= 1) v += __shfl_xor_sync(0xffffffffu, v, d);
    if ((t & 31) == 0) sd[t >> 5] = v;
    __syncthreads();
    if (t < 32) {
        int s = sd[t];
#pragma unroll
        for (int d = 16; d; d >>= 1) s += __shfl_xor_sync(0xffffffffu, s, d);
        if (t == 0) g_blk[blockIdx.x] = s;
    }
}
__global__ void scan_b(int nb) {
    if (threadIdx.x == 0) {
        int run = 0;
        for (int i = 0; i < nb; i++) { g_blkscan[i] = run; run += g_blk[i]; }
    }
}
__global__ void scan_c(int n) {
    __shared__ int wsum[32];
    int t = threadIdx.x;
    int idx = blockIdx.x * 1024 + t;
    int v = (idx < n) ? g_cnt[idx] : 0;
    int lane = t & 31, w = t >> 5;
    int inc = v;
#pragma unroll
    for (int d = 1; d < 32; d <<= 1) {
        int u = __shfl_up_sync(0xffffffffu, inc, d);
        if (lane >= d) inc += u;
    }
    if (lane == 31) wsum[w] = inc;
    __syncthreads();
    if (w == 0) {
        int s = wsum[lane];
        int si = s;
#pragma unroll
        for (int d = 1; d < 32; d <<= 1) {
            int u = __shfl_up_sync(0xffffffffu, si, d);
            if (lane >= d) si += u;
        }
        wsum[lane] = si - s;   // exclusive offsets of warps
    }
    __syncthreads();
    int excl = (inc - v) + wsum[w] + g_blkscan[blockIdx.x];
    if (idx < n) { g_off[idx] = excl; g_cur[idx] = excl; }
    if (idx == n - 1) g_off[n] = excl + v;
}

// ---------------------------------------------------------------------------
__global__ void scat_kernel(const int* __restrict__ ei, int ne) {
    int i = blockIdx.x * blockDim.x + threadIdx.x;
    if (i < ne) {
        int d = ei[ne + i];
        int p = atomicAdd(&g_cur[d], 1);
        g_sorted[p] = ei[i];               // src = edge_index[0]
    }
}

// ---------------------------------------------------------------------------
// Warp per destination node. Lane l owns dims [4l,4l+4) => head = l>>2.
// Softmax without max-subtraction (logits bounded ~|10|):
//   out = (sum_e w_e * xh[src_e]) / (sum_e w_e),  w = exp(leakyrelu(asrc+adst))
// Self loop included explicitly (reference concatenates all loops).
__global__ void agg_kernel(const float* __restrict__ bias,
                           float* __restrict__ out, int n)
{
    int warp = (blockIdx.x * blockDim.x + threadIdx.x) >> 5;
    int lane = threadIdx.x & 31;
    if (warp >= n) return;
    int h = lane >> 2;
    float adst = g_adst[warp * 8 + h];

    // self loop
    float asl = g_asrc[warp * 8 + h];
    float lg = asl + adst;
    float wgt = __expf(lg > 0.f ? lg : 0.2f * lg);
    float4 xv = *(const float4*)&g_xh[warp * 128 + lane * 4];
    float denom = wgt;
    float4 acc;
    acc.x = wgt * xv.x; acc.y = wgt * xv.y; acc.z = wgt * xv.z; acc.w = wgt * xv.w;

    int e0 = g_off[warp], e1 = g_off[warp + 1];
    for (int e = e0; e < e1; e++) {
        int s = g_sorted[e];
        float as = g_asrc[s * 8 + h];
        float l2 = as + adst;
        float w2 = __expf(l2 > 0.f ? l2 : 0.2f * l2);
        float4 v = *(const float4*)&g_xh[s * 128 + lane * 4];
        denom += w2;
        acc.x += w2 * v.x; acc.y += w2 * v.y;
        acc.z += w2 * v.z; acc.w += w2 * v.w;
    }
    float inv = 1.f / denom;
    float4 bv = *(const float4*)&bias[lane * 4];
    float4 o;
    o.x = acc.x * inv + bv.x;
    o.y = acc.y * inv + bv.y;
    o.z = acc.z * inv + bv.z;
    o.w = acc.w * inv + bv.w;
    *(float4*)&out[warp * 128 + lane * 4] = o;
}

// ---------------------------------------------------------------------------
extern "C" void kernel_launch(void* const* d_in, const int* in_sizes, int n_in,
                              void* d_out, int out_size)
{
    const float* x    = (const float*)d_in[0];
    const int*   ei   = (const int*)d_in[1];
    const float* W    = (const float*)d_in[2];
    const float* bp   = (const float*)d_in[3];
    const float* as_  = (const float*)d_in[4];
    const float* ad_  = (const float*)d_in[5];
    const float* bias = (const float*)d_in[6];
    float* out = (float*)d_out;

    const int n  = in_sizes[0] / 128;
    const int ne = in_sizes[1] / 2;
    const int nb = (n + 1023) / 1024;

    zero_kernel<<<(n + 255) / 256, 256>>>(n);
    gemm_kernel<<<(n + 63) / 64, 256>>>(x, W, bp, n);
    att_kernel<<<(n + 7) / 8, 256>>>(as_, ad_, n);
    hist_kernel<<<(ne + 255) / 256, 256>>>(ei, ne);
    scan_a<<<nb, 1024>>>(n);
    scan_b<<<1, 32>>>(nb);
    scan_c<<<nb, 1024>>>(n);
    scat_kernel<<<(ne + 255) / 256, 256>>>(ei, ne);
    agg_kernel<<<(n + 7) / 8, 256>>>(bias, out, n);
}

// round 5
// speedup vs baseline: 1.5109x; 1.5109x over previous
#include <cuda_runtime.h>
#include <cuda_fp16.h>
#include <cuda_bf16.h>

#define NMAX 100000
#define EMAX 1600000

// ---- device scratch (no allocations allowed) ----
static __device__ __half g_xh_h[NMAX * 128];   // projected features fp16 [N,128]
static __device__ float g_asrc[NMAX * 8];      // per-node src logits [N,H]
static __device__ float g_adst[NMAX * 8];      // per-node dst logits [N,H]
static __device__ int   g_cnt[NMAX];           // in-degree histogram
static __device__ int   g_off[NMAX + 1];       // CSR offsets
static __device__ int   g_cur[NMAX];           // scatter cursors
static __device__ int   g_blk[128];            // scan partials
static __device__ int   g_blkscan[128];        // scanned partials
static __device__ int   g_sorted[EMAX];        // src ids grouped by dst

// ---------------------------------------------------------------------------
__global__ void zero_kernel(int n) {
    int i = blockIdx.x * blockDim.x + threadIdx.x;
    if (i < n) g_cnt[i] = 0;
}

// ---------------------------------------------------------------------------
__device__ __forceinline__ unsigned f2tf32(float f) {
    unsigned r;
    asm("cvt.rna.tf32.f32 %0, %1;" : "=r"(r) : "f"(f));
    return r;
}
__device__ __forceinline__ void mma_tf32(float* c,
    unsigned a0, unsigned a1, unsigned a2, unsigned a3,
    unsigned b0, unsigned b1)
{
    asm volatile(
        "mma.sync.aligned.m16n8k8.row.col.f32.tf32.tf32.f32 "
        "{%0,%1,%2,%3}, {%4,%5,%6,%7}, {%8,%9}, {%0,%1,%2,%3};"
        : "+f"(c[0]), "+f"(c[1]), "+f"(c[2]), "+f"(c[3])
        : "r"(a0), "r"(a1), "r"(a2), "r"(a3), "r"(b0), "r"(b1));
}

// xh = x @ W^T + b  via tf32 tensor-core mma. 128x128 tile/block, 8 warps,
// each warp computes 16 rows x 128 cols. K processed in chunks of 32.
// smem row stride 36 => bank = (4*row + k) mod 32 = lane : conflict-free frags.
__global__ __launch_bounds__(256) void gemm_kernel(
    const float* __restrict__ x, const float* __restrict__ W,
    const float* __restrict__ b, int n)
{
    __shared__ unsigned ws[128 * 36];   // W[j][k] chunk, tf32 bits
    __shared__ unsigned xs[128 * 36];   // x[r][k] chunk, tf32 bits
    const int tid = threadIdx.x;
    const int lane = tid & 31, warp = tid >> 5;
    const int row0 = blockIdx.x * 128;
    const int g = lane >> 2;        // groupID
    const int tg = lane & 3;        // thread-in-group

    float acc[16][4];
#pragma unroll
    for (int t = 0; t < 16; t++)
#pragma unroll
        for (int c = 0; c < 4; c++) acc[t][c] = 0.f;

    for (int kk = 0; kk < 128; kk += 32) {
#pragma unroll
        for (int i = 0; i < 4; i++) {           // W chunk: 128x32
            int id = tid + i * 256;             // 0..1023 float4s
            int j = id >> 3, kq = (id & 7) * 4;
            float4 v = *(const float4*)&W[j * 128 + kk + kq];
            unsigned* d = &ws[j * 36 + kq];
            d[0] = f2tf32(v.x); d[1] = f2tf32(v.y);
            d[2] = f2tf32(v.z); d[3] = f2tf32(v.w);
        }
#pragma unroll
        for (int i = 0; i < 4; i++) {           // x chunk: 128x32
            int id = tid + i * 256;
            int r = id >> 3, kq = (id & 7) * 4;
            int row = row0 + r;
            float4 v = (row < n) ? *(const float4*)&x[row * 128 + kk + kq]
                                 : make_float4(0.f, 0.f, 0.f, 0.f);
            unsigned* d = &xs[r * 36 + kq];
            d[0] = f2tf32(v.x); d[1] = f2tf32(v.y);
            d[2] = f2tf32(v.z); d[3] = f2tf32(v.w);
        }
        __syncthreads();
        const int rA = warp * 16 + g;
#pragma unroll
        for (int ks = 0; ks < 32; ks += 8) {
            unsigned a0 = xs[rA * 36 + ks + tg];
            unsigned a1 = xs[(rA + 8) * 36 + ks + tg];
            unsigned a2 = xs[rA * 36 + ks + 4 + tg];
            unsigned a3 = xs[(rA + 8) * 36 + ks + 4 + tg];
#pragma unroll
            for (int t = 0; t < 16; t++) {
                int jn = t * 8 + g;
                unsigned b0 = ws[jn * 36 + ks + tg];
                unsigned b1 = ws[jn * 36 + ks + 4 + tg];
                mma_tf32(acc[t], a0, a1, a2, a3, b0, b1);
            }
        }
        __syncthreads();
    }

    // epilogue: +bias, store fp16
    const int r0 = row0 + warp * 16 + g;
#pragma unroll
    for (int t = 0; t < 16; t++) {
        int j0 = t * 8 + 2 * tg;
        float bx = b[j0], by = b[j0 + 1];
        if (r0 < n)
            *(__half2*)&g_xh_h[r0 * 128 + j0] =
                __floats2half2_rn(acc[t][0] + bx, acc[t][1] + by);
        if (r0 + 8 < n)
            *(__half2*)&g_xh_h[(r0 + 8) * 128 + j0] =
                __floats2half2_rn(acc[t][2] + bx, acc[t][3] + by);
    }
}

// ---------------------------------------------------------------------------
// a_src[n,h] = sum_d xh[n,h,d]*att_src[h,d];  same for a_dst.  Warp per node.
__global__ void att_kernel(const float* __restrict__ att_s,
                           const float* __restrict__ att_d, int n)
{
    int warp = (blockIdx.x * blockDim.x + threadIdx.x) >> 5;
    int lane = threadIdx.x & 31;
    if (warp >= n) return;
    uint2 u = *(const uint2*)&g_xh_h[warp * 128 + lane * 4];
    float2 f0 = __half22float2(*reinterpret_cast<__half2*>(&u.x));
    float2 f1 = __half22float2(*reinterpret_cast<__half2*>(&u.y));
    float4 sa = *(const float4*)&att_s[lane * 4];
    float4 da = *(const float4*)&att_d[lane * 4];
    float s = f0.x * sa.x + f0.y * sa.y + f1.x * sa.z + f1.y * sa.w;
    float d = f0.x * da.x + f0.y * da.y + f1.x * da.z + f1.y * da.w;
    s += __shfl_xor_sync(0xffffffffu, s, 1);
    s += __shfl_xor_sync(0xffffffffu, s, 2);
    d += __shfl_xor_sync(0xffffffffu, d, 1);
    d += __shfl_xor_sync(0xffffffffu, d, 2);
    if ((lane & 3) == 0) {
        g_asrc[warp * 8 + (lane >> 2)] = s;
        g_adst[warp * 8 + (lane >> 2)] = d;
    }
}

// ---------------------------------------------------------------------------
__global__ void hist_kernel(const int* __restrict__ ei, int ne) {
    int i = blockIdx.x * blockDim.x + threadIdx.x;
    if (i < ne) atomicAdd(&g_cnt[ei[ne + i]], 1);   // dst = edge_index[1]
}

// ---- 3-step exclusive scan over g_cnt (chunks of 1024) --------------------
__global__ void scan_a(int n) {
    __shared__ int sd[32];
    int t = threadIdx.x;
    int idx = blockIdx.x * 1024 + t;
    int v = (idx < n) ? g_cnt[idx] : 0;
#pragma unroll
    for (int d = 16; d; d >>= 1) v += __shfl_xor_sync(0xffffffffu, v, d);
    if ((t & 31) == 0) sd[t >> 5] = v;
    __syncthreads();
    if (t < 32) {
        int s = sd[t];
#pragma unroll
        for (int d = 16; d; d >>= 1) s += __shfl_xor_sync(0xffffffffu, s, d);
        if (t == 0) g_blk[blockIdx.x] = s;
    }
}
__global__ void scan_b(int nb) {
    if (threadIdx.x == 0) {
        int run = 0;
        for (int i = 0; i < nb; i++) { g_blkscan[i] = run; run += g_blk[i]; }
    }
}
__global__ void scan_c(int n) {
    __shared__ int wsum[32];
    int t = threadIdx.x;
    int idx = blockIdx.x * 1024 + t;
    int v = (idx < n) ? g_cnt[idx] : 0;
    int lane = t & 31, w = t >> 5;
    int inc = v;
#pragma unroll
    for (int d = 1; d < 32; d <<= 1) {
        int u = __shfl_up_sync(0xffffffffu, inc, d);
        if (lane >= d) inc += u;
    }
    if (lane == 31) wsum[w] = inc;
    __syncthreads();
    if (w == 0) {
        int s = wsum[lane];
        int si = s;
#pragma unroll
        for (int d = 1; d < 32; d <<= 1) {
            int u = __shfl_up_sync(0xffffffffu, si, d);
            if (lane >= d) si += u;
        }
        wsum[lane] = si - s;   // exclusive offsets of warps
    }
    __syncthreads();
    int excl = (inc - v) + wsum[w] + g_blkscan[blockIdx.x];
    if (idx < n) { g_off[idx] = excl; g_cur[idx] = excl; }
    if (idx == n - 1) g_off[n] = excl + v;
}

// ---------------------------------------------------------------------------
__global__ void scat_kernel(const int* __restrict__ ei, int ne) {
    int i = blockIdx.x * blockDim.x + threadIdx.x;
    if (i < ne) {
        int d = ei[ne + i];
        int p = atomicAdd(&g_cur[d], 1);
        g_sorted[p] = ei[i];               // src = edge_index[0]
    }
}

// ---------------------------------------------------------------------------
// Warp per destination node. Lane l owns dims [4l,4l+4) => head = l>>2.
// Softmax without max-subtraction (logits bounded):
//   out = (sum_e w_e * xh[src_e]) / (sum_e w_e),  w = exp(leakyrelu(asrc+adst))
__global__ void agg_kernel(const float* __restrict__ bias,
                           float* __restrict__ out, int n)
{
    int warp = (blockIdx.x * blockDim.x + threadIdx.x) >> 5;
    int lane = threadIdx.x & 31;
    if (warp >= n) return;
    int h = lane >> 2;
    float adst = g_adst[warp * 8 + h];

    // self loop
    float asl = g_asrc[warp * 8 + h];
    float lg = asl + adst;
    float wgt = __expf(lg > 0.f ? lg : 0.2f * lg);
    uint2 u = *(const uint2*)&g_xh_h[warp * 128 + lane * 4];
    float2 f0 = __half22float2(*reinterpret_cast<__half2*>(&u.x));
    float2 f1 = __half22float2(*reinterpret_cast<__half2*>(&u.y));
    float denom = wgt;
    float4 acc;
    acc.x = wgt * f0.x; acc.y = wgt * f0.y;
    acc.z = wgt * f1.x; acc.w = wgt * f1.y;

    int e0 = g_off[warp], e1 = g_off[warp + 1];
    for (int e = e0; e < e1; e++) {
        int s = g_sorted[e];
        float as = g_asrc[s * 8 + h];
        float l2 = as + adst;
        float w2 = __expf(l2 > 0.f ? l2 : 0.2f * l2);
        uint2 uv = *(const uint2*)&g_xh_h[s * 128 + lane * 4];
        float2 v0 = __half22float2(*reinterpret_cast<__half2*>(&uv.x));
        float2 v1 = __half22float2(*reinterpret_cast<__half2*>(&uv.y));
        denom += w2;
        acc.x += w2 * v0.x; acc.y += w2 * v0.y;
        acc.z += w2 * v1.x; acc.w += w2 * v1.y;
    }
    float inv = 1.f / denom;
    float4 bv = *(const float4*)&bias[lane * 4];
    float4 o;
    o.x = acc.x * inv + bv.x;
    o.y = acc.y * inv + bv.y;
    o.z = acc.z * inv + bv.z;
    o.w = acc.w * inv + bv.w;
    *(float4*)&out[warp * 128 + lane * 4] = o;
}

// ---------------------------------------------------------------------------
extern "C" void kernel_launch(void* const* d_in, const int* in_sizes, int n_in,
                              void* d_out, int out_size)
{
    const float* x    = (const float*)d_in[0];
    const int*   ei   = (const int*)d_in[1];
    const float* W    = (const float*)d_in[2];
    const float* bp   = (const float*)d_in[3];
    const float* as_  = (const float*)d_in[4];
    const float* ad_  = (const float*)d_in[5];
    const float* bias = (const float*)d_in[6];
    float* out = (float*)d_out;

    const int n  = in_sizes[0] / 128;
    const int ne = in_sizes[1] / 2;
    const int nb = (n + 1023) / 1024;

    zero_kernel<<<(n + 255) / 256, 256>>>(n);
    gemm_kernel<<<(n + 127) / 128, 256>>>(x, W, bp, n);
    att_kernel<<<(n + 7) / 8, 256>>>(as_, ad_, n);
    hist_kernel<<<(ne + 255) / 256, 256>>>(ei, ne);
    scan_a<<<nb, 1024>>>(n);
    scan_b<<<1, 32>>>(nb);
    scan_c<<<nb, 1024>>>(n);
    scat_kernel<<<(ne + 255) / 256, 256>>>(ei, ne);
    agg_kernel<<<(n + 7) / 8, 256>>>(bias, out, n);
}

// round 7
// speedup vs baseline: 1.5138x; 1.0019x over previous
#include <cuda_runtime.h>
#include <cuda_fp16.h>
#include <cuda_bf16.h>

#define NMAX 100000
#define EMAX 1600000

// ---- device scratch (no allocations allowed) ----
static __device__ __half g_xh_h[NMAX * 128];   // projected features fp16 [N,128]
static __device__ float g_asrc[NMAX * 8];      // per-node src logits [N,H]
static __device__ float g_adst[NMAX * 8];      // per-node dst logits [N,H]
static __device__ int   g_cnt[NMAX];           // in-degree histogram
static __device__ int   g_off[NMAX + 1];       // CSR offsets
static __device__ int   g_cur[NMAX];           // scatter cursors
static __device__ int   g_blk[128];            // scan partials
static __device__ int   g_blkscan[128];        // scanned partials
static __device__ int   g_sorted[EMAX];        // src ids grouped by dst

// ---------------------------------------------------------------------------
__global__ void zero_kernel(int n) {
    int i = blockIdx.x * blockDim.x + threadIdx.x;
    if (i < n) g_cnt[i] = 0;
}

// ---------------------------------------------------------------------------
__device__ __forceinline__ unsigned f2tf32(float f) {
    unsigned r;
    asm("cvt.rna.tf32.f32 %0, %1;" : "=r"(r) : "f"(f));
    return r;
}
__device__ __forceinline__ void mma_tf32(float* c,
    unsigned a0, unsigned a1, unsigned a2, unsigned a3,
    unsigned b0, unsigned b1)
{
    asm volatile(
        "mma.sync.aligned.m16n8k8.row.col.f32.tf32.tf32.f32 "
        "{%0,%1,%2,%3}, {%4,%5,%6,%7}, {%8,%9}, {%0,%1,%2,%3};"
        : "+f"(c[0]), "+f"(c[1]), "+f"(c[2]), "+f"(c[3])
        : "r"(a0), "r"(a1), "r"(a2), "r"(a3), "r"(b0), "r"(b1));
}

// xh = x @ W^T + b via tf32 mma; att logits fused into the epilogue.
// 128x128 tile/block, 8 warps, warp computes rows [w*16, w*16+16) x 128 cols.
// smem row stride 36 => conflict-free fragment LDS.
__global__ __launch_bounds__(256, 2) void gemm_kernel(
    const float* __restrict__ x, const float* __restrict__ W,
    const float* __restrict__ b,
    const float* __restrict__ att_s, const float* __restrict__ att_d, int n)
{
    __shared__ unsigned ws[128 * 36];   // W[j][k] chunk, tf32 bits
    __shared__ unsigned xs[128 * 36];   // x[r][k] chunk, tf32 bits
    __shared__ float as_sm[128], ad_sm[128], b_sm[128];
    const int tid = threadIdx.x;
    const int lane = tid & 31, warp = tid >> 5;
    const int row0 = blockIdx.x * 128;
    const int g = lane >> 2;        // groupID (row selector)
    const int tg = lane & 3;        // thread-in-group (col selector)

    if (tid < 128) {
        as_sm[tid] = att_s[tid];
        ad_sm[tid] = att_d[tid];
        b_sm[tid]  = b[tid];
    }

    float acc[16][4];
#pragma unroll
    for (int t = 0; t < 16; t++)
#pragma unroll
        for (int c = 0; c < 4; c++) acc[t][c] = 0.f;

    for (int kk = 0; kk < 128; kk += 32) {
#pragma unroll
        for (int i = 0; i < 4; i++) {           // W chunk: 128x32
            int id = tid + i * 256;             // float4 index
            int j = id >> 3, kq = (id & 7) * 4;
            float4 v = *(const float4*)&W[j * 128 + kk + kq];
            unsigned* d = &ws[j * 36 + kq];
            d[0] = f2tf32(v.x); d[1] = f2tf32(v.y);
            d[2] = f2tf32(v.z); d[3] = f2tf32(v.w);
        }
#pragma unroll
        for (int i = 0; i < 4; i++) {           // x chunk: 128x32
            int id = tid + i * 256;
            int r = id >> 3, kq = (id & 7) * 4;
            int row = row0 + r;
            float4 v = (row < n) ? *(const float4*)&x[row * 128 + kk + kq]
                                 : make_float4(0.f, 0.f, 0.f, 0.f);
            unsigned* d = &xs[r * 36 + kq];
            d[0] = f2tf32(v.x); d[1] = f2tf32(v.y);
            d[2] = f2tf32(v.z); d[3] = f2tf32(v.w);
        }
        __syncthreads();
        const int rA = warp * 16 + g;
#pragma unroll
        for (int ks = 0; ks < 32; ks += 8) {
            unsigned a0 = xs[rA * 36 + ks + tg];
            unsigned a1 = xs[(rA + 8) * 36 + ks + tg];
            unsigned a2 = xs[rA * 36 + ks + 4 + tg];
            unsigned a3 = xs[(rA + 8) * 36 + ks + 4 + tg];
#pragma unroll
            for (int t = 0; t < 16; t++) {
                int jn = t * 8 + g;
                unsigned b0 = ws[jn * 36 + ks + tg];
                unsigned b1 = ws[jn * 36 + ks + 4 + tg];
                mma_tf32(acc[t], a0, a1, a2, a3, b0, b1);
            }
        }
        __syncthreads();
    }

    // epilogue: +bias, store fp16, fused per-head attention logits
    const int r0 = row0 + warp * 16 + g;
    const bool okA = (r0 < n), okB = (r0 + 8 < n);
#pragma unroll
    for (int h = 0; h < 8; h++) {
        float sA = 0.f, dA = 0.f, sB = 0.f, dB = 0.f;
#pragma unroll
        for (int tt = 0; tt < 2; tt++) {
            const int t  = 2 * h + tt;
            const int j0 = t * 8 + 2 * tg;
            float bx = b_sm[j0], by = b_sm[j0 + 1];
            float v00 = acc[t][0] + bx, v01 = acc[t][1] + by;
            float v10 = acc[t][2] + bx, v11 = acc[t][3] + by;
            if (okA) *(__half2*)&g_xh_h[r0 * 128 + j0] = __floats2half2_rn(v00, v01);
            if (okB) *(__half2*)&g_xh_h[(r0 + 8) * 128 + j0] = __floats2half2_rn(v10, v11);
            float a0 = as_sm[j0], a1 = as_sm[j0 + 1];
            float q0 = ad_sm[j0], q1 = ad_sm[j0 + 1];
            sA += v00 * a0 + v01 * a1;  dA += v00 * q0 + v01 * q1;
            sB += v10 * a0 + v11 * a1;  dB += v10 * q0 + v11 * q1;
        }
        // reduce over the 4 lanes of the group (consecutive lanes)
        sA += __shfl_xor_sync(0xffffffffu, sA, 1); sA += __shfl_xor_sync(0xffffffffu, sA, 2);
        dA += __shfl_xor_sync(0xffffffffu, dA, 1); dA += __shfl_xor_sync(0xffffffffu, dA, 2);
        sB += __shfl_xor_sync(0xffffffffu, sB, 1); sB += __shfl_xor_sync(0xffffffffu, sB, 2);
        dB += __shfl_xor_sync(0xffffffffu, dB, 1); dB += __shfl_xor_sync(0xffffffffu, dB, 2);
        if ((h & 3) == tg) {
            if (okA) { g_asrc[r0 * 8 + h] = sA; g_adst[r0 * 8 + h] = dA; }
            if (okB) { g_asrc[(r0 + 8) * 8 + h] = sB; g_adst[(r0 + 8) * 8 + h] = dB; }
        }
    }
}

// ---------------------------------------------------------------------------
__global__ void hist4_kernel(const int* __restrict__ ei, int ne) {
    int i = blockIdx.x * blockDim.x + threadIdx.x;
    int ne4 = ne >> 2;
    if (i < ne4) {
        int4 d = ((const int4*)(ei + ne))[i];
        atomicAdd(&g_cnt[d.x], 1);
        atomicAdd(&g_cnt[d.y], 1);
        atomicAdd(&g_cnt[d.z], 1);
        atomicAdd(&g_cnt[d.w], 1);
    }
}
__global__ void hist_kernel(const int* __restrict__ ei, int ne) {
    int i = blockIdx.x * blockDim.x + threadIdx.x;
    if (i < ne) atomicAdd(&g_cnt[ei[ne + i]], 1);
}

// ---- 3-step exclusive scan over g_cnt (chunks of 1024) --------------------
__global__ void scan_a(int n) {
    __shared__ int sd[32];
    int t = threadIdx.x;
    int idx = blockIdx.x * 1024 + t;
    int v = (idx < n) ? g_cnt[idx] : 0;
#pragma unroll
    for (int d = 16; d; d >>= 1) v += __shfl_xor_sync(0xffffffffu, v, d);
    if ((t & 31) == 0) sd[t >> 5] = v;
    __syncthreads();
    if (t < 32) {
        int s = sd[t];
#pragma unroll
        for (int d = 16; d; d >>= 1) s += __shfl_xor_sync(0xffffffffu, s, d);
        if (t == 0) g_blk[blockIdx.x] = s;
    }
}
__global__ void scan_b(int nb) {
    if (threadIdx.x == 0) {
        int run = 0;
        for (int i = 0; i < nb; i++) { g_blkscan[i] = run; run += g_blk[i]; }
    }
}
__global__ void scan_c(int n) {
    __shared__ int wsum[32];
    int t = threadIdx.x;
    int idx = blockIdx.x * 1024 + t;
    int v = (idx < n) ? g_cnt[idx] : 0;
    int lane = t & 31, w = t >> 5;
    int inc = v;
#pragma unroll
    for (int d = 1; d < 32; d <<= 1) {
        int u = __shfl_up_sync(0xffffffffu, inc, d);
        if (lane >= d) inc += u;
    }
    if (lane == 31) wsum[w] = inc;
    __syncthreads();
    if (w == 0) {
        int s = wsum[lane];
        int si = s;
#pragma unroll
        for (int d = 1; d < 32; d <<= 1) {
            int u = __shfl_up_sync(0xffffffffu, si, d);
            if (lane >= d) si += u;
        }
        wsum[lane] = si - s;   // exclusive offsets of warps
    }
    __syncthreads();
    int excl = (inc - v) + wsum[w] + g_blkscan[blockIdx.x];
    if (idx < n) { g_off[idx] = excl; g_cur[idx] = excl; }
    if (idx == n - 1) g_off[n] = excl + v;
}

// ---------------------------------------------------------------------------
__global__ void scat4_kernel(const int* __restrict__ ei, int ne) {
    int i = blockIdx.x * blockDim.x + threadIdx.x;
    int ne4 = ne >> 2;
    if (i < ne4) {
        int4 s = ((const int4*)ei)[i];
        int4 d = ((const int4*)(ei + ne))[i];
        int p0 = atomicAdd(&g_cur[d.x], 1);
        int p1 = atomicAdd(&g_cur[d.y], 1);
        int p2 = atomicAdd(&g_cur[d.z], 1);
        int p3 = atomicAdd(&g_cur[d.w], 1);
        g_sorted[p0] = s.x; g_sorted[p1] = s.y;
        g_sorted[p2] = s.z; g_sorted[p3] = s.w;
    }
}
__global__ void scat_kernel(const int* __restrict__ ei, int ne) {
    int i = blockIdx.x * blockDim.x + threadIdx.x;
    if (i < ne) {
        int d = ei[ne + i];
        int p = atomicAdd(&g_cur[d], 1);
        g_sorted[p] = ei[i];
    }
}

// ---------------------------------------------------------------------------
// Warp per destination node. Lane l owns dims [4l,4l+4) => head = l>>2.
// Softmax without max-subtraction (logits bounded):
//   out = (sum_e w_e * xh[src_e]) / (sum_e w_e),  w = exp(leakyrelu(asrc+adst))
// Edge loop unrolled x4 with batched loads for MLP.
__global__ void agg_kernel(const float* __restrict__ bias,
                           float* __restrict__ out, int n)
{
    int warp = (blockIdx.x * blockDim.x + threadIdx.x) >> 5;
    int lane = threadIdx.x & 31;
    if (warp >= n) return;
    int h = lane >> 2;
    float adst = g_adst[warp * 8 + h];

    // self loop
    float asl = g_asrc[warp * 8 + h];
    float lg = asl + adst;
    float wgt = __expf(lg > 0.f ? lg : 0.2f * lg);
    uint2 u = *(const uint2*)&g_xh_h[warp * 128 + lane * 4];
    float2 f0 = __half22float2(*reinterpret_cast<__half2*>(&u.x));
    float2 f1 = __half22float2(*reinterpret_cast<__half2*>(&u.y));
    float denom = wgt;
    float4 acc;
    acc.x = wgt * f0.x; acc.y = wgt * f0.y;
    acc.z = wgt * f1.x; acc.w = wgt * f1.y;

    const int e1 = g_off[warp + 1];
    int e = g_off[warp];
    for (; e + 3 < e1; e += 4) {
        int s0 = g_sorted[e],     s1 = g_sorted[e + 1];
        int s2 = g_sorted[e + 2], s3 = g_sorted[e + 3];
        float a0 = g_asrc[s0 * 8 + h], a1 = g_asrc[s1 * 8 + h];
        float a2 = g_asrc[s2 * 8 + h], a3 = g_asrc[s3 * 8 + h];
        uint2 v0 = *(const uint2*)&g_xh_h[s0 * 128 + lane * 4];
        uint2 v1 = *(const uint2*)&g_xh_h[s1 * 128 + lane * 4];
        uint2 v2 = *(const uint2*)&g_xh_h[s2 * 128 + lane * 4];
        uint2 v3 = *(const uint2*)&g_xh_h[s3 * 128 + lane * 4];
        float l0 = a0 + adst, l1 = a1 + adst, l2 = a2 + adst, l3 = a3 + adst;
        float w0 = __expf(l0 > 0.f ? l0 : 0.2f * l0);
        float w1 = __expf(l1 > 0.f ? l1 : 0.2f * l1);
        float w2 = __expf(l2 > 0.f ? l2 : 0.2f * l2);
        float w3 = __expf(l3 > 0.f ? l3 : 0.2f * l3);
        denom += w0 + w1 + w2 + w3;
        float2 p, q;
        p = __half22float2(*reinterpret_cast<__half2*>(&v0.x));
        q = __half22float2(*reinterpret_cast<__half2*>(&v0.y));
        acc.x += w0 * p.x; acc.y += w0 * p.y; acc.z += w0 * q.x; acc.w += w0 * q.y;
        p = __half22float2(*reinterpret_cast<__half2*>(&v1.x));
        q = __half22float2(*reinterpret_cast<__half2*>(&v1.y));
        acc.x += w1 * p.x; acc.y += w1 * p.y; acc.z += w1 * q.x; acc.w += w1 * q.y;
        p = __half22float2(*reinterpret_cast<__half2*>(&v2.x));
        q = __half22float2(*reinterpret_cast<__half2*>(&v2.y));
        acc.x += w2 * p.x; acc.y += w2 * p.y; acc.z += w2 * q.x; acc.w += w2 * q.y;
        p = __half22float2(*reinterpret_cast<__half2*>(&v3.x));
        q = __half22float2(*reinterpret_cast<__half2*>(&v3.y));
        acc.x += w3 * p.x; acc.y += w3 * p.y; acc.z += w3 * q.x; acc.w += w3 * q.y;
    }
    for (; e < e1; e++) {
        int s = g_sorted[e];
        float as = g_asrc[s * 8 + h];
        float l2 = as + adst;
        float w2 = __expf(l2 > 0.f ? l2 : 0.2f * l2);
        uint2 uv = *(const uint2*)&g_xh_h[s * 128 + lane * 4];
        float2 v0 = __half22float2(*reinterpret_cast<__half2*>(&uv.x));
        float2 v1 = __half22float2(*reinterpret_cast<__half2*>(&uv.y));
        denom += w2;
        acc.x += w2 * v0.x; acc.y += w2 * v0.y;
        acc.z += w2 * v1.x; acc.w += w2 * v1.y;
    }
    float inv = 1.f / denom;
    float4 bv = *(const float4*)&bias[lane * 4];
    float4 o;
    o.x = acc.x * inv + bv.x;
    o.y = acc.y * inv + bv.y;
    o.z = acc.z * inv + bv.z;
    o.w = acc.w * inv + bv.w;
    *(float4*)&out[warp * 128 + lane * 4] = o;
}

// ---------------------------------------------------------------------------
extern "C" void kernel_launch(void* const* d_in, const int* in_sizes, int n_in,
                              void* d_out, int out_size)
{
    const float* x    = (const float*)d_in[0];
    const int*   ei   = (const int*)d_in[1];
    const float* W    = (const float*)d_in[2];
    const float* bp   = (const float*)d_in[3];
    const float* as_  = (const float*)d_in[4];
    const float* ad_  = (const float*)d_in[5];
    const float* bias = (const float*)d_in[6];
    float* out = (float*)d_out;

    const int n  = in_sizes[0] / 128;
    const int ne = in_sizes[1] / 2;
    const int nb = (n + 1023) / 1024;

    zero_kernel<<<(n + 255) / 256, 256>>>(n);
    gemm_kernel<<<(n + 127) / 128, 256>>>(x, W, bp, as_, ad_, n);
    if ((ne & 3) == 0) {
        hist4_kernel<<<(ne / 4 + 255) / 256, 256>>>(ei, ne);
    } else {
        hist_kernel<<<(ne + 255) / 256, 256>>>(ei, ne);
    }
    scan_a<<<nb, 1024>>>(n);
    scan_b<<<1, 32>>>(nb);
    scan_c<<<nb, 1024>>>(n);
    if ((ne & 3) == 0) {
        scat4_kernel<<<(ne / 4 + 255) / 256, 256>>>(ei, ne);
    } else {
        scat_kernel<<<(ne + 255) / 256, 256>>>(ei, ne);
    }
    agg_kernel<<<(n + 7) / 8, 256>>>(bias, out, n);
}